// round 14
// baseline (speedup 1.0000x reference)
#include <cuda_runtime.h>
#include <cuda_bf16.h>
#include <cuda_fp16.h>
#include <stdint.h>

#define BATCH 2
#define SEQ 2048
#define DM 1024
#define NH 16
#define DH 64
#define MTOT (BATCH*SEQ)
#define QSCALE 0.18033688f   // log2(e) / sqrt(64)

// ---------------- device-global scratch (all single fp16) ----------------
__device__ __align__(16) __half g_x[3ull*MTOT*DM];           // q/k/v inputs
__device__ __align__(16) __half g_wt[3ull*DM*DM];            // W_{q,k,v} transposed
__device__ __align__(16) __half g_wot[(size_t)DM*DM];        // W_o transposed
__device__ __align__(16) __half g_q[(size_t)MTOT*DM];
__device__ __align__(16) __half g_k[(size_t)MTOT*DM];
__device__ __align__(16) __half g_vt[(size_t)MTOT*DM];       // [bh*64+d][seq]
__device__ __align__(16) __half g_z[(size_t)MTOT*DM];

// ---------------- helpers ----------------
__device__ __forceinline__ uint32_t smem_u32(const void* p) {
    uint32_t a;
    asm("{ .reg .u64 t; cvta.to.shared.u64 t, %1; cvt.u32.u64 %0, t; }" : "=r"(a) : "l"(p));
    return a;
}
#define SWZ128(o) ((o) ^ (((o) >> 3) & 0x70))

__device__ __forceinline__ void mma_f16(float* c, const uint32_t* a, uint32_t b0, uint32_t b1) {
    asm volatile("mma.sync.aligned.m16n8k16.row.col.f32.f16.f16.f32 "
        "{%0,%1,%2,%3}, {%4,%5,%6,%7}, {%8,%9}, {%0,%1,%2,%3};"
        : "+f"(c[0]), "+f"(c[1]), "+f"(c[2]), "+f"(c[3])
        : "r"(a[0]), "r"(a[1]), "r"(a[2]), "r"(a[3]), "r"(b0), "r"(b1));
}
__device__ __forceinline__ void ldsm4(uint32_t* r, uint32_t a) {
    asm volatile("ldmatrix.sync.aligned.m8n8.x4.shared.b16 {%0,%1,%2,%3}, [%4];"
        : "=r"(r[0]), "=r"(r[1]), "=r"(r[2]), "=r"(r[3]) : "r"(a));
}
__device__ __forceinline__ uint32_t fraddr(uint32_t base, int lane, int r0, int ku) {
    int g = lane >> 3, r8 = lane & 7;
    return base + SWZ128(((r0 + r8 + ((g & 1) << 3)) << 7) + ((ku + (g >> 1)) << 4));
}
// pack 2 floats into f16x2 (first arg -> low half) and exp2 both
__device__ __forceinline__ uint32_t h2exp2(float lo, float hi) {
    uint32_t d;
    asm("cvt.rn.f16x2.f32 %0, %1, %2;" : "=r"(d) : "f"(hi), "f"(lo));
    asm("ex2.approx.f16x2 %0, %0;" : "+r"(d));
    return d;
}
__device__ __forceinline__ uint32_t hadd2(uint32_t a, uint32_t b) {
    uint32_t d;
    asm("add.f16x2 %0, %1, %2;" : "=r"(d) : "r"(a), "r"(b));
    return d;
}
__device__ __forceinline__ void cpa16(uint32_t dst, const void* src) {
    asm volatile("cp.async.cg.shared.global [%0], [%1], 16;" :: "r"(dst), "l"(src) : "memory");
}
#define CP_COMMIT() asm volatile("cp.async.commit_group;" ::: "memory")
#define CP_WAIT(n)  asm volatile("cp.async.wait_group %0;" :: "n"(n) : "memory")

// ---------------- conversion kernels ----------------
__global__ __launch_bounds__(256) void cvt_x_kernel(
    const float* __restrict__ q, const float* __restrict__ k, const float* __restrict__ v) {
    const int z = blockIdx.y;
    const float* __restrict__ src = (z == 0) ? q : (z == 1) ? k : v;
    size_t base = (size_t)z * MTOT * DM;
    size_t i = ((size_t)blockIdx.x * 256 + threadIdx.x) * 8;
    union { __half b[8]; uint4 u; } H;
    #pragma unroll
    for (int j = 0; j < 8; j += 4) {
        float4 f = *(const float4*)(src + i + j);
        H.b[j + 0] = __float2half_rn(f.x);
        H.b[j + 1] = __float2half_rn(f.y);
        H.b[j + 2] = __float2half_rn(f.z);
        H.b[j + 3] = __float2half_rn(f.w);
    }
    *(uint4*)(g_x + base + i) = H.u;
}

// W[w][h][k][e] -> g_wt[w][(h*64+e)][k]
__global__ __launch_bounds__(256) void cvt_wqkv_kernel(
    const float* __restrict__ wq, const float* __restrict__ wk, const float* __restrict__ wv) {
    __shared__ float s[32][33];
    const int w = blockIdx.z >> 4, hh = blockIdx.z & 15;
    const float* __restrict__ W = ((w == 0) ? wq : (w == 1) ? wk : wv) + (size_t)hh * DM * DH;
    const int k0 = blockIdx.x * 32, e0 = blockIdx.y * 32;
    const int tx = threadIdx.x, ty = threadIdx.y;
    #pragma unroll
    for (int i = 0; i < 4; i++)
        s[ty + 8 * i][tx] = W[(size_t)(k0 + ty + 8 * i) * DH + e0 + tx];
    __syncthreads();
    size_t dbase = (size_t)w * DM * DM;
    #pragma unroll
    for (int i = 0; i < 4; i++) {
        size_t o = dbase + (size_t)(hh * 64 + e0 + ty + 8 * i) * DM + k0 + tx;
        g_wt[o] = __float2half_rn(s[tx][ty + 8 * i]);
    }
}

// WO[k][d] -> g_wot[d][k]
__global__ __launch_bounds__(256) void cvt_wo_kernel(const float* __restrict__ W) {
    __shared__ float s[32][33];
    const int k0 = blockIdx.x * 32, d0 = blockIdx.y * 32;
    const int tx = threadIdx.x, ty = threadIdx.y;
    #pragma unroll
    for (int i = 0; i < 4; i++)
        s[ty + 8 * i][tx] = W[(size_t)(k0 + ty + 8 * i) * DM + d0 + tx];
    __syncthreads();
    #pragma unroll
    for (int i = 0; i < 4; i++) {
        size_t o = (size_t)(d0 + ty + 8 * i) * DM + k0 + tx;
        g_wot[o] = __float2half_rn(s[tx][ty + 8 * i]);
    }
}

// ---------------- fp16 1-term GEMM: C[128x128] = X @ W^T (+bias) ----------------
// 256 threads (8 warps: 4M x 2N; warp tile 32m x 64n). K-chunk 64.
// 3 stages x 32KB (A@0 B@16K), single barrier per chunk. 2 CTAs/SM.
#define PJ_STAGE 32768

__device__ __forceinline__ void proj_copy(
    const __half* __restrict__ X, const __half* __restrict__ W,
    uint32_t sb, int st, int m0, int n0, int k0, int t)
{
    #pragma unroll
    for (int u = 0; u < 4; u++) {
        int idx = u * 256 + t;
        int row = idx >> 3, c = idx & 7;
        uint32_t so = SWZ128((row << 7) + (c << 4));
        cpa16(sb + st + so,         X + (size_t)(m0 + row) * DM + k0 + c * 8);
        cpa16(sb + st + 16384 + so, W + (size_t)(n0 + row) * DM + k0 + c * 8);
    }
}

__device__ __forceinline__ void proj_compute(uint32_t sb, int st, int lane,
                                             int wm, int wn, float acc[2][8][4])
{
    #pragma unroll
    for (int ks = 0; ks < 4; ks++) {
        uint32_t aH[2][4];
        #pragma unroll
        for (int mt = 0; mt < 2; mt++)
            ldsm4(aH[mt], fraddr(sb + st, lane, wm + mt * 16, 2 * ks));
        #pragma unroll
        for (int np = 0; np < 4; np++) {
            uint32_t bH[4];
            ldsm4(bH, fraddr(sb + st + 16384, lane, wn + np * 16, 2 * ks));
            mma_f16(acc[0][2*np],   aH[0], bH[0], bH[2]);
            mma_f16(acc[0][2*np+1], aH[0], bH[1], bH[3]);
            mma_f16(acc[1][2*np],   aH[1], bH[0], bH[2]);
            mma_f16(acc[1][2*np+1], aH[1], bH[1], bH[3]);
        }
    }
}

// mode: 0=Q (scale, fp16), 1=K (fp16), 2=V (fp16 transposed), 3=fp32 out
__device__ __forceinline__ void proj_core(
    const __half* __restrict__ X, const __half* __restrict__ W,
    const float* __restrict__ bias,
    __half* __restrict__ Oh, float* __restrict__ Of,
    char* sm, int m0, int n0, int mode)
{
    const int t = threadIdx.x, lane = t & 31, w = t >> 5;
    const uint32_t sb = smem_u32(sm);
    const int wm = (w & 3) * 32, wn = (w >> 2) * 64;
    float acc[2][8][4] = {};

    proj_copy(X, W, sb, 0, m0, n0, 0, t);
    CP_COMMIT();
    proj_copy(X, W, sb, PJ_STAGE, m0, n0, 64, t);
    CP_COMMIT();

    for (int kc = 0; kc < 16; kc++) {
        if (kc + 1 < 16) { CP_WAIT(1); } else { CP_WAIT(0); }
        __syncthreads();                 // stage kc ready for all; stage (kc-1)%3 free
        if (kc + 2 < 16) {
            proj_copy(X, W, sb, ((kc + 2) % 3) * PJ_STAGE, m0, n0, (kc + 2) * 64, t);
            CP_COMMIT();
        }
        proj_compute(sb, (kc % 3) * PJ_STAGE, lane, wm, wn, acc);
    }

    const float scale = (mode == 0) ? QSCALE : 1.0f;
    #pragma unroll
    for (int mt = 0; mt < 2; mt++)
        #pragma unroll
        for (int np = 0; np < 8; np++)
            #pragma unroll
            for (int h2 = 0; h2 < 2; h2++) {
                int m = m0 + wm + mt * 16 + (lane >> 2) + h2 * 8;
                int n = n0 + wn + np * 8 + 2 * (lane & 3);
                float v0 = (acc[mt][np][h2 * 2]     + bias[n])     * scale;
                float v1 = (acc[mt][np][h2 * 2 + 1] + bias[n + 1]) * scale;
                if (mode == 3) {
                    *(float2*)(Of + (size_t)m * DM + n) = make_float2(v0, v1);
                } else if (mode == 2) {
                    int bb = m >> 11, seq = m & 2047;
                    size_t o0 = ((size_t)(bb * NH + (n >> 6)) * DH + (n & 63)) * SEQ + seq;
                    size_t o1 = ((size_t)(bb * NH + ((n+1) >> 6)) * DH + ((n+1) & 63)) * SEQ + seq;
                    Oh[o0] = __float2half_rn(v0);
                    Oh[o1] = __float2half_rn(v1);
                } else {
                    __half2 hp = __floats2half2_rn(v0, v1);
                    *(uint32_t*)(Oh + (size_t)m * DM + n) = *(uint32_t*)&hp;
                }
            }
}

__global__ __launch_bounds__(256, 2) void qkv_proj_mma(const float* bq, const float* bk,
                                                       const float* bv) {
    extern __shared__ char sm[];
    const int z = blockIdx.z;
    proj_core(g_x + (size_t)z * MTOT * DM, g_wt + (size_t)z * DM * DM,
              (z == 0) ? bq : (z == 1) ? bk : bv,
              (z == 0) ? g_q : (z == 1) ? g_k : g_vt,
              nullptr, sm, blockIdx.y * 128, blockIdx.x * 128, z);
}

__global__ __launch_bounds__(256, 2) void out_proj_mma(const float* bo, float* out) {
    extern __shared__ char sm[];
    proj_core(g_z, g_wot, bo, nullptr, out,
              sm, blockIdx.y * 128, blockIdx.x * 128, 3);
}

// ---------------- FA2 attention: single fp16, 3-stage K/V, 1 barrier/iter ----------------
// smem: Q@0 (16K); stage s @ 16K + 16K*(kb%3): K 0, V 8K. 64KB total. 2 CTAs/SM.
#define AT_ST0 16384
#define AT_SS  16384

__device__ __forceinline__ void attn_copy(uint32_t sb, int kb, int b, int hd, int t) {
    const int st = AT_ST0 + (kb % 3) * AT_SS;
    const int k0 = kb * 64;
    #pragma unroll
    for (int u = 0; u < 2; u++) {
        int idx = u * 256 + t;
        int row = idx >> 3, c = idx & 7;
        uint32_t so = SWZ128((row << 7) + (c << 4));
        cpa16(sb + st + so,
              g_k + (size_t)(b * SEQ + k0 + row) * DM + hd * DH + c * 8);
        cpa16(sb + st + 8192 + so,
              g_vt + ((size_t)((b * NH + hd) * DH + row)) * SEQ + k0 + c * 8);
    }
}

__global__ __launch_bounds__(256, 2) void attn_mma() {
    extern __shared__ char sm[];
    const uint32_t sb = smem_u32(sm);
    const int t = threadIdx.x, lane = t & 31, w = t >> 5;
    const int qb = (gridDim.x - 1) - blockIdx.x;    // largest-first
    const int hd = blockIdx.y, b = blockIdx.z;
    const int q0 = qb * 128, wq = w * 16;
    const int nkb = 2 * qb + 2;

    attn_copy(sb, 0, b, hd, t);
    CP_COMMIT();
    if (nkb > 1) attn_copy(sb, 1, b, hd, t);
    CP_COMMIT();

    // Q tile (128 x 64 fp16), plain stores (each thread: half a row)
    {
        int r = t >> 1, half = t & 1;
        const __half* __restrict__ src =
            g_q + (size_t)(b * SEQ + q0 + r) * DM + hd * DH + half * 32;
        #pragma unroll
        for (int i = 0; i < 4; i++)
            *(uint4*)(sm + SWZ128((r << 7) + ((half * 4 + i) << 4))) =
                *(const uint4*)(src + i * 8);
    }
    __syncthreads();

    uint32_t qH[4][4];
    #pragma unroll
    for (int ks = 0; ks < 4; ks++)
        ldsm4(qH[ks], fraddr(sb, lane, wq, 2 * ks));

    float oacc[8][4] = {};
    float lsum[2] = {0.0f, 0.0f};

    for (int kb = 0; kb < nkb; kb++) {
        const int k0 = kb * 64;
        const int st = AT_ST0 + (kb % 3) * AT_SS;
        if (kb + 1 < nkb) { CP_WAIT(1); } else { CP_WAIT(0); }
        __syncthreads();
        if (kb + 2 < nkb) {
            attn_copy(sb, kb + 2, b, hd, t);
            CP_COMMIT();
        }

        // warp-level skip: this warp's rows [q0+wq, q0+wq+15] all < k0 => all masked
        if (k0 > q0 + wq + 15) continue;

        // S = Q K^T (1 term, fp32 acc)
        float sacc[8][4] = {};
        #pragma unroll
        for (int ds = 0; ds < 4; ds++)
            #pragma unroll
            for (int np = 0; np < 4; np++) {
                uint32_t kH[4];
                ldsm4(kH, fraddr(sb + st, lane, np * 16, 2 * ds));
                mma_f16(sacc[2*np],   qH[ds], kH[0], kH[2]);
                mma_f16(sacc[2*np+1], qH[ds], kH[1], kH[3]);
            }

        // causal mask (diagonal tiles only)
        if (kb >= 2 * qb) {
            #pragma unroll
            for (int np = 0; np < 8; np++)
                #pragma unroll
                for (int j = 0; j < 4; j++) {
                    int kg = k0 + np * 8 + 2 * (lane & 3) + (j & 1);
                    int qg = q0 + wq + (lane >> 2) + (j >> 1) * 8;
                    if (kg > qg) sacc[np][j] = -30000.0f;
                }
        }

        // f16x2 exp2; accumulate l in f16x2
        uint32_t pe[8][2];
        uint32_t la0 = 0, la1 = 0;
        #pragma unroll
        for (int np = 0; np < 8; np++) {
            pe[np][0] = h2exp2(sacc[np][0], sacc[np][1]);
            pe[np][1] = h2exp2(sacc[np][2], sacc[np][3]);
            la0 = hadd2(la0, pe[np][0]);
            la1 = hadd2(la1, pe[np][1]);
        }
        {
            float2 f0 = __half22float2(*reinterpret_cast<__half2*>(&la0));
            float2 f1 = __half22float2(*reinterpret_cast<__half2*>(&la1));
            lsum[0] += f0.x + f0.y;
            lsum[1] += f1.x + f1.y;
        }

        // PV: P fp16 (A-frag = pe), V single fp16, fp32 acc
        #pragma unroll
        for (int ks = 0; ks < 4; ks++) {
            uint32_t pf[4] = { pe[2*ks][0], pe[2*ks][1], pe[2*ks+1][0], pe[2*ks+1][1] };
            #pragma unroll
            for (int dp = 0; dp < 4; dp++) {
                uint32_t vH[4];
                ldsm4(vH, fraddr(sb + st + 8192, lane, dp * 16, 2 * ks));
                mma_f16(oacc[2*dp],   pf, vH[0], vH[2]);
                mma_f16(oacc[2*dp+1], pf, vH[1], vH[3]);
            }
        }
    }

    #pragma unroll
    for (int i = 0; i < 2; i++) {
        lsum[i] += __shfl_xor_sync(0xffffffffu, lsum[i], 1);
        lsum[i] += __shfl_xor_sync(0xffffffffu, lsum[i], 2);
    }
    float inv0 = 1.0f / lsum[0], inv1 = 1.0f / lsum[1];

    // z = O / l, single fp16, [b*SEQ+q][hd*64+d]
    #pragma unroll
    for (int np = 0; np < 8; np++)
        #pragma unroll
        for (int h2 = 0; h2 < 2; h2++) {
            int q = q0 + wq + (lane >> 2) + h2 * 8;
            int d = np * 8 + 2 * (lane & 3);
            float inv = h2 ? inv1 : inv0;
            __half2 hp = __floats2half2_rn(oacc[np][h2 * 2] * inv,
                                           oacc[np][h2 * 2 + 1] * inv);
            size_t o = (size_t)(b * SEQ + q) * DM + hd * DH + d;
            *(uint32_t*)(g_z + o) = *(uint32_t*)&hp;
        }
}

// ---------------------------------------------------------------------------
extern "C" void kernel_launch(void* const* d_in, const int* in_sizes, int n_in,
                              void* d_out, int out_size)
{
    const float* qin = (const float*)d_in[0];
    const float* kin = (const float*)d_in[1];
    const float* vin = (const float*)d_in[2];
    const float* WQ  = (const float*)d_in[3];
    const float* WK  = (const float*)d_in[4];
    const float* WV  = (const float*)d_in[5];
    const float* WO  = (const float*)d_in[6];
    const float* bQ  = (const float*)d_in[7];
    const float* bK  = (const float*)d_in[8];
    const float* bV  = (const float*)d_in[9];
    const float* bO  = (const float*)d_in[10];
    float* out = (float*)d_out;

    cudaFuncSetAttribute(qkv_proj_mma, cudaFuncAttributeMaxDynamicSharedMemorySize, 98304);
    cudaFuncSetAttribute(out_proj_mma, cudaFuncAttributeMaxDynamicSharedMemorySize, 98304);
    cudaFuncSetAttribute(attn_mma,     cudaFuncAttributeMaxDynamicSharedMemorySize, 65536);

    cvt_x_kernel<<<dim3(MTOT * DM / 8 / 256, 3), 256>>>(qin, kin, vin);
    cvt_wqkv_kernel<<<dim3(32, 2, 48), dim3(32, 8)>>>(WQ, WK, WV);
    cvt_wo_kernel<<<dim3(32, 32), dim3(32, 8)>>>(WO);

    qkv_proj_mma<<<dim3(DM / 128, MTOT / 128, 3), 256, 98304>>>(bQ, bK, bV);
    attn_mma<<<dim3(SEQ / 128, NH, BATCH), 256, 49152 + 16384>>>();
    out_proj_mma<<<dim3(DM / 128, MTOT / 128), 256, 98304>>>(bO, out);
}

// round 15
// speedup vs baseline: 1.0758x; 1.0758x over previous
#include <cuda_runtime.h>
#include <cuda_bf16.h>
#include <cuda_fp16.h>
#include <stdint.h>

#define BATCH 2
#define SEQ 2048
#define DM 1024
#define NH 16
#define DH 64
#define MTOT (BATCH*SEQ)
#define QSCALE 0.18033688f   // log2(e) / sqrt(64)

// ---------------- device-global scratch (all single fp16) ----------------
__device__ __align__(16) __half g_x[3ull*MTOT*DM];           // q/k/v inputs
__device__ __align__(16) __half g_wt[3ull*DM*DM];            // W_{q,k,v} transposed
__device__ __align__(16) __half g_wot[(size_t)DM*DM];        // W_o transposed
__device__ __align__(16) __half g_q[(size_t)MTOT*DM];
__device__ __align__(16) __half g_k[(size_t)MTOT*DM];
__device__ __align__(16) __half g_vt[(size_t)MTOT*DM];       // [bh*64+d][seq]
__device__ __align__(16) __half g_z[(size_t)MTOT*DM];

// ---------------- helpers ----------------
__device__ __forceinline__ uint32_t smem_u32(const void* p) {
    uint32_t a;
    asm("{ .reg .u64 t; cvta.to.shared.u64 t, %1; cvt.u32.u64 %0, t; }" : "=r"(a) : "l"(p));
    return a;
}
#define SWZ128(o) ((o) ^ (((o) >> 3) & 0x70))

__device__ __forceinline__ void mma_f16(float* c, const uint32_t* a, uint32_t b0, uint32_t b1) {
    asm volatile("mma.sync.aligned.m16n8k16.row.col.f32.f16.f16.f32 "
        "{%0,%1,%2,%3}, {%4,%5,%6,%7}, {%8,%9}, {%0,%1,%2,%3};"
        : "+f"(c[0]), "+f"(c[1]), "+f"(c[2]), "+f"(c[3])
        : "r"(a[0]), "r"(a[1]), "r"(a[2]), "r"(a[3]), "r"(b0), "r"(b1));
}
__device__ __forceinline__ void ldsm4(uint32_t* r, uint32_t a) {
    asm volatile("ldmatrix.sync.aligned.m8n8.x4.shared.b16 {%0,%1,%2,%3}, [%4];"
        : "=r"(r[0]), "=r"(r[1]), "=r"(r[2]), "=r"(r[3]) : "r"(a));
}
__device__ __forceinline__ uint32_t fraddr(uint32_t base, int lane, int r0, int ku) {
    int g = lane >> 3, r8 = lane & 7;
    return base + SWZ128(((r0 + r8 + ((g & 1) << 3)) << 7) + ((ku + (g >> 1)) << 4));
}
// pack 2 floats into f16x2 (first arg -> low half) and exp2 both
__device__ __forceinline__ uint32_t h2exp2(float lo, float hi) {
    uint32_t d;
    asm("cvt.rn.f16x2.f32 %0, %1, %2;" : "=r"(d) : "f"(hi), "f"(lo));
    asm("ex2.approx.f16x2 %0, %0;" : "+r"(d));
    return d;
}
__device__ __forceinline__ uint32_t hadd2(uint32_t a, uint32_t b) {
    uint32_t d;
    asm("add.f16x2 %0, %1, %2;" : "=r"(d) : "r"(a), "r"(b));
    return d;
}
__device__ __forceinline__ void cpa16(uint32_t dst, const void* src) {
    asm volatile("cp.async.cg.shared.global [%0], [%1], 16;" :: "r"(dst), "l"(src) : "memory");
}
#define CP_COMMIT() asm volatile("cp.async.commit_group;" ::: "memory")
#define CP_WAIT(n)  asm volatile("cp.async.wait_group %0;" :: "n"(n) : "memory")

// ---------------- merged conversion kernel ----------------
// flat grid: [0, 6144)        cvt_x   (z = bid/2048, block = bid%2048)
//            [6144, 9216)     cvt_wqkv (i = bid-6144: kx=i%32, ey=(i/32)%2, zh=i/64)
//            [9216, 10240)    cvt_wo  (i = bid-9216: kx=i%32, dy=i/32)
__global__ __launch_bounds__(256) void cvt_all_kernel(
    const float* __restrict__ qin, const float* __restrict__ kin, const float* __restrict__ vin,
    const float* __restrict__ WQ,  const float* __restrict__ WK,  const float* __restrict__ WV,
    const float* __restrict__ WO)
{
    __shared__ float s[32][33];
    const int bid = blockIdx.x;
    const int t = threadIdx.x;

    if (bid < 6144) {
        const int z = bid >> 11;
        const float* __restrict__ src = (z == 0) ? qin : (z == 1) ? kin : vin;
        size_t base = (size_t)z * MTOT * DM;
        size_t i = ((size_t)(bid & 2047) * 256 + t) * 8;
        union { __half b[8]; uint4 u; } H;
        #pragma unroll
        for (int j = 0; j < 8; j += 4) {
            float4 f = *(const float4*)(src + i + j);
            H.b[j + 0] = __float2half_rn(f.x);
            H.b[j + 1] = __float2half_rn(f.y);
            H.b[j + 2] = __float2half_rn(f.z);
            H.b[j + 3] = __float2half_rn(f.w);
        }
        *(uint4*)(g_x + base + i) = H.u;
    } else if (bid < 9216) {
        const int i = bid - 6144;
        const int kx = i & 31, ey = (i >> 5) & 1, zh = i >> 6;   // zh in [0,48)
        const int w = zh >> 4, hh = zh & 15;
        const float* __restrict__ W = ((w == 0) ? WQ : (w == 1) ? WK : WV) + (size_t)hh * DM * DH;
        const int k0 = kx * 32, e0 = ey * 32;
        const int tx = t & 31, ty = t >> 5;
        #pragma unroll
        for (int j = 0; j < 4; j++)
            s[ty + 8 * j][tx] = W[(size_t)(k0 + ty + 8 * j) * DH + e0 + tx];
        __syncthreads();
        size_t dbase = (size_t)w * DM * DM;
        #pragma unroll
        for (int j = 0; j < 4; j++) {
            size_t o = dbase + (size_t)(hh * 64 + e0 + ty + 8 * j) * DM + k0 + tx;
            g_wt[o] = __float2half_rn(s[tx][ty + 8 * j]);
        }
    } else {
        const int i = bid - 9216;
        const int kx = i & 31, dy = i >> 5;
        const int k0 = kx * 32, d0 = dy * 32;
        const int tx = t & 31, ty = t >> 5;
        #pragma unroll
        for (int j = 0; j < 4; j++)
            s[ty + 8 * j][tx] = WO[(size_t)(k0 + ty + 8 * j) * DM + d0 + tx];
        __syncthreads();
        #pragma unroll
        for (int j = 0; j < 4; j++) {
            size_t o = (size_t)(d0 + ty + 8 * j) * DM + k0 + tx;
            g_wot[o] = __float2half_rn(s[tx][ty + 8 * j]);
        }
    }
}

// ---------------- fp16 1-term GEMM: C[128x128] = X @ W^T (+bias) ----------------
// 256 threads (8 warps: 4M x 2N; warp tile 32m x 64n). K-chunk 64.
// Stage 32KB: A@0 B@16K. 2 stages = 64KB dynamic. 2 CTAs/SM.
#define PJ_STAGE 32768

__device__ __forceinline__ void proj_copy(
    const __half* __restrict__ X, const __half* __restrict__ W,
    uint32_t sb, int st, int m0, int n0, int k0, int t)
{
    #pragma unroll
    for (int u = 0; u < 4; u++) {
        int idx = u * 256 + t;
        int row = idx >> 3, c = idx & 7;
        uint32_t so = SWZ128((row << 7) + (c << 4));
        cpa16(sb + st + so,         X + (size_t)(m0 + row) * DM + k0 + c * 8);
        cpa16(sb + st + 16384 + so, W + (size_t)(n0 + row) * DM + k0 + c * 8);
    }
}

__device__ __forceinline__ void proj_compute(uint32_t sb, int st, int lane,
                                             int wm, int wn, float acc[2][8][4])
{
    #pragma unroll
    for (int ks = 0; ks < 4; ks++) {
        uint32_t aH[2][4];
        #pragma unroll
        for (int mt = 0; mt < 2; mt++)
            ldsm4(aH[mt], fraddr(sb + st, lane, wm + mt * 16, 2 * ks));
        #pragma unroll
        for (int np = 0; np < 4; np++) {
            uint32_t bH[4];
            ldsm4(bH, fraddr(sb + st + 16384, lane, wn + np * 16, 2 * ks));
            mma_f16(acc[0][2*np],   aH[0], bH[0], bH[2]);
            mma_f16(acc[0][2*np+1], aH[0], bH[1], bH[3]);
            mma_f16(acc[1][2*np],   aH[1], bH[0], bH[2]);
            mma_f16(acc[1][2*np+1], aH[1], bH[1], bH[3]);
        }
    }
}

// mode: 0=Q (scale, fp16), 1=K (fp16), 2=V (fp16 transposed), 3=fp32 out
__device__ __forceinline__ void proj_core(
    const __half* __restrict__ X, const __half* __restrict__ W,
    const float* __restrict__ bias,
    __half* __restrict__ Oh, float* __restrict__ Of,
    char* sm, int m0, int n0, int mode)
{
    const int t = threadIdx.x, lane = t & 31, w = t >> 5;
    const uint32_t sb = smem_u32(sm);
    const int wm = (w & 3) * 32, wn = (w >> 2) * 64;
    float acc[2][8][4] = {};

    proj_copy(X, W, sb, 0, m0, n0, 0, t);
    CP_COMMIT();

    for (int kc = 0; kc < 16; kc++) {
        if (kc + 1 < 16) {
            proj_copy(X, W, sb, ((kc + 1) & 1) * PJ_STAGE, m0, n0, (kc + 1) * 64, t);
            CP_COMMIT();
            CP_WAIT(1);
        } else {
            CP_WAIT(0);
        }
        __syncthreads();
        proj_compute(sb, (kc & 1) * PJ_STAGE, lane, wm, wn, acc);
        __syncthreads();
    }

    const float scale = (mode == 0) ? QSCALE : 1.0f;
    #pragma unroll
    for (int mt = 0; mt < 2; mt++)
        #pragma unroll
        for (int np = 0; np < 8; np++)
            #pragma unroll
            for (int h2 = 0; h2 < 2; h2++) {
                int m = m0 + wm + mt * 16 + (lane >> 2) + h2 * 8;
                int n = n0 + wn + np * 8 + 2 * (lane & 3);
                float v0 = (acc[mt][np][h2 * 2]     + bias[n])     * scale;
                float v1 = (acc[mt][np][h2 * 2 + 1] + bias[n + 1]) * scale;
                if (mode == 3) {
                    *(float2*)(Of + (size_t)m * DM + n) = make_float2(v0, v1);
                } else if (mode == 2) {
                    int bb = m >> 11, seq = m & 2047;
                    size_t o0 = ((size_t)(bb * NH + (n >> 6)) * DH + (n & 63)) * SEQ + seq;
                    size_t o1 = ((size_t)(bb * NH + ((n+1) >> 6)) * DH + ((n+1) & 63)) * SEQ + seq;
                    Oh[o0] = __float2half_rn(v0);
                    Oh[o1] = __float2half_rn(v1);
                } else {
                    __half2 hp = __floats2half2_rn(v0, v1);
                    *(uint32_t*)(Oh + (size_t)m * DM + n) = *(uint32_t*)&hp;
                }
            }
}

__global__ __launch_bounds__(256, 2) void qkv_proj_mma(const float* bq, const float* bk,
                                                       const float* bv) {
    extern __shared__ char sm[];
    const int z = blockIdx.z;
    proj_core(g_x + (size_t)z * MTOT * DM, g_wt + (size_t)z * DM * DM,
              (z == 0) ? bq : (z == 1) ? bk : bv,
              (z == 0) ? g_q : (z == 1) ? g_k : g_vt,
              nullptr, sm, blockIdx.y * 128, blockIdx.x * 128, z);
}

__global__ __launch_bounds__(256, 2) void out_proj_mma(const float* bo, float* out) {
    extern __shared__ char sm[];
    proj_core(g_z, g_wot, bo, nullptr, out,
              sm, blockIdx.y * 128, blockIdx.x * 128, 3);
}

// ---------------- FA2 attention: single fp16, 2-stage K/V, 2 CTAs/SM ----------------
// smem: Q@0 (16K); stage s @ 16K+16K*s: K 0, V 8K. 48KB total.
#define AT_ST0 16384
#define AT_SS  16384

__device__ __forceinline__ void attn_copy(uint32_t sb, int kb, int b, int hd, int t) {
    const int st = AT_ST0 + (kb & 1) * AT_SS;
    const int k0 = kb * 64;
    #pragma unroll
    for (int u = 0; u < 2; u++) {
        int idx = u * 256 + t;
        int row = idx >> 3, c = idx & 7;
        uint32_t so = SWZ128((row << 7) + (c << 4));
        cpa16(sb + st + so,
              g_k + (size_t)(b * SEQ + k0 + row) * DM + hd * DH + c * 8);
        cpa16(sb + st + 8192 + so,
              g_vt + ((size_t)((b * NH + hd) * DH + row)) * SEQ + k0 + c * 8);
    }
}

__global__ __launch_bounds__(256, 2) void attn_mma() {
    extern __shared__ char sm[];
    const uint32_t sb = smem_u32(sm);
    const int t = threadIdx.x, lane = t & 31, w = t >> 5;
    const int qb = (gridDim.x - 1) - blockIdx.x;    // largest-first
    const int hd = blockIdx.y, b = blockIdx.z;
    const int q0 = qb * 128, wq = w * 16;
    const int nkb = 2 * qb + 2;

    attn_copy(sb, 0, b, hd, t);
    CP_COMMIT();

    // Q tile (128 x 64 fp16), plain stores (each thread: half a row)
    {
        int r = t >> 1, half = t & 1;
        const __half* __restrict__ src =
            g_q + (size_t)(b * SEQ + q0 + r) * DM + hd * DH + half * 32;
        #pragma unroll
        for (int i = 0; i < 4; i++)
            *(uint4*)(sm + SWZ128((r << 7) + ((half * 4 + i) << 4))) =
                *(const uint4*)(src + i * 8);
    }
    __syncthreads();

    uint32_t qH[4][4];
    #pragma unroll
    for (int ks = 0; ks < 4; ks++)
        ldsm4(qH[ks], fraddr(sb, lane, wq, 2 * ks));

    float oacc[8][4] = {};
    float lsum[2] = {0.0f, 0.0f};

    for (int kb = 0; kb < nkb; kb++) {
        const int k0 = kb * 64;
        const int st = AT_ST0 + (kb & 1) * AT_SS;
        if (kb + 1 < nkb) {
            attn_copy(sb, kb + 1, b, hd, t);
            CP_COMMIT();
            CP_WAIT(1);
        } else {
            CP_WAIT(0);
        }
        __syncthreads();

        // warp-skip: fully-masked warps contribute exactly zero -> skip compute.
        // Barriers stay outside the guard (warp-uniform condition).
        if (k0 <= q0 + wq + 15) {
            // S = Q K^T (1 term)
            float sacc[8][4] = {};
            #pragma unroll
            for (int ds = 0; ds < 4; ds++)
                #pragma unroll
                for (int np = 0; np < 4; np++) {
                    uint32_t kH[4];
                    ldsm4(kH, fraddr(sb + st, lane, np * 16, 2 * ds));
                    mma_f16(sacc[2*np],   qH[ds], kH[0], kH[2]);
                    mma_f16(sacc[2*np+1], qH[ds], kH[1], kH[3]);
                }

            // causal mask (diagonal tiles only)
            if (kb >= 2 * qb) {
                #pragma unroll
                for (int np = 0; np < 8; np++)
                    #pragma unroll
                    for (int j = 0; j < 4; j++) {
                        int kg = k0 + np * 8 + 2 * (lane & 3) + (j & 1);
                        int qg = q0 + wq + (lane >> 2) + (j >> 1) * 8;
                        if (kg > qg) sacc[np][j] = -30000.0f;
                    }
            }

            // f16x2 exp2; accumulate l in f16x2
            uint32_t pe[8][2];
            uint32_t la0 = 0, la1 = 0;
            #pragma unroll
            for (int np = 0; np < 8; np++) {
                pe[np][0] = h2exp2(sacc[np][0], sacc[np][1]);
                pe[np][1] = h2exp2(sacc[np][2], sacc[np][3]);
                la0 = hadd2(la0, pe[np][0]);
                la1 = hadd2(la1, pe[np][1]);
            }
            {
                float2 f0 = __half22float2(*reinterpret_cast<__half2*>(&la0));
                float2 f1 = __half22float2(*reinterpret_cast<__half2*>(&la1));
                lsum[0] += f0.x + f0.y;
                lsum[1] += f1.x + f1.y;
            }

            // PV: P fp16 (A-frag = pe), V single fp16
            #pragma unroll
            for (int ks = 0; ks < 4; ks++) {
                uint32_t pf[4] = { pe[2*ks][0], pe[2*ks][1], pe[2*ks+1][0], pe[2*ks+1][1] };
                #pragma unroll
                for (int dp = 0; dp < 4; dp++) {
                    uint32_t vH[4];
                    ldsm4(vH, fraddr(sb + st + 8192, lane, dp * 16, 2 * ks));
                    mma_f16(oacc[2*dp],   pf, vH[0], vH[2]);
                    mma_f16(oacc[2*dp+1], pf, vH[1], vH[3]);
                }
            }
        }
        __syncthreads();
    }

    #pragma unroll
    for (int i = 0; i < 2; i++) {
        lsum[i] += __shfl_xor_sync(0xffffffffu, lsum[i], 1);
        lsum[i] += __shfl_xor_sync(0xffffffffu, lsum[i], 2);
    }
    float inv0 = 1.0f / lsum[0], inv1 = 1.0f / lsum[1];

    // z = O / l, single fp16, [b*SEQ+q][hd*64+d]
    #pragma unroll
    for (int np = 0; np < 8; np++)
        #pragma unroll
        for (int h2 = 0; h2 < 2; h2++) {
            int q = q0 + wq + (lane >> 2) + h2 * 8;
            int d = np * 8 + 2 * (lane & 3);
            float inv = h2 ? inv1 : inv0;
            __half2 hp = __floats2half2_rn(oacc[np][h2 * 2] * inv,
                                           oacc[np][h2 * 2 + 1] * inv);
            size_t o = (size_t)(b * SEQ + q) * DM + hd * DH + d;
            *(uint32_t*)(g_z + o) = *(uint32_t*)&hp;
        }
}

// ---------------------------------------------------------------------------
extern "C" void kernel_launch(void* const* d_in, const int* in_sizes, int n_in,
                              void* d_out, int out_size)
{
    const float* qin = (const float*)d_in[0];
    const float* kin = (const float*)d_in[1];
    const float* vin = (const float*)d_in[2];
    const float* WQ  = (const float*)d_in[3];
    const float* WK  = (const float*)d_in[4];
    const float* WV  = (const float*)d_in[5];
    const float* WO  = (const float*)d_in[6];
    const float* bQ  = (const float*)d_in[7];
    const float* bK  = (const float*)d_in[8];
    const float* bV  = (const float*)d_in[9];
    const float* bO  = (const float*)d_in[10];
    float* out = (float*)d_out;

    cudaFuncSetAttribute(qkv_proj_mma, cudaFuncAttributeMaxDynamicSharedMemorySize, 65536);
    cudaFuncSetAttribute(out_proj_mma, cudaFuncAttributeMaxDynamicSharedMemorySize, 65536);
    cudaFuncSetAttribute(attn_mma,     cudaFuncAttributeMaxDynamicSharedMemorySize, 49152);

    cvt_all_kernel<<<10240, 256>>>(qin, kin, vin, WQ, WK, WV, WO);

    qkv_proj_mma<<<dim3(DM / 128, MTOT / 128, 3), 256, 65536>>>(bQ, bK, bV);
    attn_mma<<<dim3(SEQ / 128, NH, BATCH), 256, 49152>>>();
    out_proj_mma<<<dim3(DM / 128, MTOT / 128), 256, 65536>>>(bO, out);
}